// round 16
// baseline (speedup 1.0000x reference)
#include <cuda_runtime.h>
#include <cstdint>

// EdgeFeaturizer: per-row 12-NN (lexicographic (dist, idx), radius-masked) +
// Gaussian RBF expansion over 50 centers.
// Two rows per block, software-pipelined: row1's global loads are in flight
// while row0's selection/epilogue phases run.
//
// Output layout (float32, flattened tuple in reference return order):
//   [0          .. N*K*2)          edge_index  (src, nbr) pairs, row-major
//   [N*K*2      .. N*K*2+N*K*50)   edge_features row-major [N*K, 50]

#define N_ATOMS    8192
#define KNN        12
#define NBINS      50
#define TPB        256
#define F4PT       (N_ATOMS / 4 / TPB)   // 8 float4 per thread per row
#define CAND_MAX   256
#define THRESH     0.006f     // lambda = 49.1 expected candidates/row;
                              // P(C < 12) ~ 3e-8/row -> exact fallback below
#define MAXRAD     8.0f

__device__ __forceinline__ unsigned long long warp_min_u64(unsigned long long v) {
#pragma unroll
    for (int off = 16; off; off >>= 1) {
        unsigned long long o = __shfl_xor_sync(0xffffffffu, v, off);
        v = (o < v) ? o : v;
    }
    return v;
}

__device__ __forceinline__ void insert12(unsigned long long (&best)[KNN],
                                         unsigned long long key) {
    if (key < best[KNN - 1]) {
#pragma unroll
        for (int s = 0; s < KNN; ++s) {
            if (key < best[s]) {
                unsigned long long t = best[s];
                best[s] = key;
                key = t;
            }
        }
    }
}

__device__ __forceinline__ void load8(const float* __restrict__ dm, int row,
                                      int tid, float4* v) {
    const float4* rp = (const float4*)(dm + (size_t)row * N_ATOMS);
#pragma unroll
    for (int i = 0; i < F4PT; ++i)
        v[i] = __ldcs(rp + tid + i * TPB);
}

__device__ __forceinline__ void filter8(const float4* v, int tid,
                                        unsigned long long* cand, int* cnt) {
#pragma unroll
    for (int i = 0; i < F4PT; ++i) {
        float a0 = v[i].x, a1 = v[i].y, a2 = v[i].z, a3 = v[i].w;
        float m = fminf(fminf(a0, a1), fminf(a2, a3));
        if (m < THRESH) {
            int base = (tid + i * TPB) * 4;
#pragma unroll
            for (int c = 0; c < 4; ++c) {
                float x = (c == 0) ? a0 : (c == 1) ? a1 : (c == 2) ? a2 : a3;
                if (x < THRESH) {
                    int p = atomicAdd(cnt, 1);
                    if (p < CAND_MAX)
                        cand[p] =
                            ((unsigned long long)__float_as_uint(x) << 32) |
                            (unsigned)(base + c);
                }
            }
        }
    }
}

// Select the 12 smallest (lexicographic (value, index)) keys of the row into
// fin[0..11]. Fast path: parallel rank selection over the candidate buffer
// (keys unique since index is embedded). Fallback: exact full-row rescan.
__device__ __forceinline__ void select_row(const float* __restrict__ dm,
                                           int row, int C, int tid,
                                           const unsigned long long* cand,
                                           unsigned long long* fin) {
    const bool fast = (C >= KNN) && (C <= CAND_MAX);
    if (fast) {
        if (tid < C) {
            const unsigned long long my = cand[tid];
            int rankv = 0;
            for (int i = 0; i < C; ++i)
                rankv += (cand[i] < my);
            if (rankv < KNN) fin[rankv] = my;
        }
    } else if (tid < 32) {
        // Statistically unreachable for this input; kept for correctness.
        unsigned long long best[KNN];
#pragma unroll
        for (int s = 0; s < KNN; ++s) best[s] = ~0ull;
        const float* r = dm + (size_t)row * N_ATOMS;
        for (int j = tid; j < N_ATOMS; j += 32) {
            float x = r[j];
            if (x <= MAXRAD) {
                unsigned long long key =
                    ((unsigned long long)__float_as_uint(x) << 32) |
                    (unsigned)j;
                insert12(best, key);
            }
        }
        int p = 0;
#pragma unroll
        for (int it = 0; it < KNN; ++it) {
            unsigned long long my = (p < KNN) ? best[p] : ~0ull;
            unsigned long long m = warp_min_u64(my);
            if (my == m) p++;
            if (tid == 0) fin[it] = m;
        }
    }
}

// edge_index writes + Gaussian-recurrence feature computation into smem.
// f(x) = exp(-12.5 (d-x)^2):  f += via f *= g, g *= kconst.
__device__ __forceinline__ void epilogue_row(int row, int tid,
                                             const unsigned long long* fin,
                                             float* feat,
                                             float* __restrict__ out) {
    if (tid < 2 * KNN) {
        const int j = tid >> 1;
        float vv = (tid & 1) ? (float)(unsigned)(fin[j] & 0xffffffffu)
                             : (float)row;
        out[(size_t)row * (2 * KNN) + tid] = vv;

        const int h = tid & 1;
        const float delta = 1.0f / 49.0f;
        const float d = __uint_as_float((unsigned)(fin[j] >> 32));
        const float x0 = (float)(h * 25) * delta;
        const float z0 = (d - x0) * 5.0f;
        float f = __expf(-0.5f * z0 * z0);
        float g = __expf(-12.5f * delta * (delta - 2.0f * (d - x0)));
        const float kconst = __expf(-25.0f * delta * delta);
        float* fr = feat + j * NBINS + h * 25;
#pragma unroll
        for (int i = 0; i < 25; ++i) {
            fr[i] = f;
            f *= g;
            g *= kconst;
        }
    }
}

__device__ __forceinline__ void store_feat(int row, int tid, const float* feat,
                                           float* __restrict__ out) {
    const size_t featBase = (size_t)N_ATOMS * (2 * KNN);
    float4* o4 = (float4*)(out + featBase) + (size_t)row * (KNN * NBINS / 4);
    const float4* s4 = (const float4*)feat;
    if (tid < KNN * NBINS / 4)  // 150 float4
        o4[tid] = s4[tid];
}

__global__ __launch_bounds__(TPB, 5) void edge_featurizer_kernel(
    const float* __restrict__ dm, float* __restrict__ out) {
    __shared__ unsigned long long cand0[CAND_MAX], cand1[CAND_MAX];
    __shared__ unsigned long long fin0[KNN], fin1[KNN];
    __shared__ __align__(16) float feat0[KNN * NBINS], feat1[KNN * NBINS];
    __shared__ int cnt0, cnt1;

    const int tid = threadIdx.x;
    const int row0 = blockIdx.x * 2;
    const int row1 = row0 + 1;
    if (tid == 0) { cnt0 = 0; cnt1 = 0; }
    __syncthreads();

    float4 v[F4PT];                 // shared register buffer for both rows

    // ---- row0 load + filter ----
    load8(dm, row0, tid, v);
    filter8(v, tid, cand0, &cnt0);

    // ---- issue row1 loads NOW: in flight during row0 selection ----
    load8(dm, row1, tid, v);

    __syncthreads();                                    // A: cand0 complete
    const int C0 = cnt0;
    select_row(dm, row0, C0, tid, cand0, fin0);         // overlaps row1 LDGs
    filter8(v, tid, cand1, &cnt1);                      // stalls until arrival

    __syncthreads();                                    // B: fin0,cand1 done
    const int C1 = cnt1;
    select_row(dm, row1, C1, tid, cand1, fin1);
    epilogue_row(row0, tid, fin0, feat0, out);

    __syncthreads();                                    // C: fin1,feat0 done
    epilogue_row(row1, tid, fin1, feat1, out);
    store_feat(row0, tid, feat0, out);

    __syncthreads();                                    // D: feat1 done
    store_feat(row1, tid, feat1, out);
}

extern "C" void kernel_launch(void* const* d_in, const int* in_sizes, int n_in,
                              void* d_out, int out_size) {
    const float* dm = (const float*)d_in[0];
    float* out = (float*)d_out;
    edge_featurizer_kernel<<<N_ATOMS / 2, TPB>>>(dm, out);
}